// round 1
// baseline (speedup 1.0000x reference)
#include <cuda_runtime.h>

// Problem constants
#define B_  4
#define S_  2048
#define D_  768
#define H_  12
#define DK_ 64
#define M_  (B_ * S_)   // 8192

// Scratch (module-static device memory; no runtime allocation)
__device__ float g_Q[(size_t)B_ * H_ * S_ * DK_];
__device__ float g_K[(size_t)B_ * H_ * S_ * DK_];
__device__ float g_V[(size_t)B_ * H_ * S_ * DK_];
__device__ float g_C[(size_t)M_ * D_];

// ---------------------------------------------------------------------------
// GEMM: C = A[M,K] @ W[N,K]^T + bias[N]
// MODE 0: C row-major [M, N]
// MODE 1: C written as [b, h, s, dk] (n0 is a multiple of 64 == DK so h is
//         constant per block)
// Tiles: BM=BN=64, BK=16. 256 threads as 16x16, 4x4 microtile per thread.
// Smem tiles stored k-major with padded row stride 68 (float4-aligned,
// conflict-free compute reads).
// ---------------------------------------------------------------------------
template <int MODE>
__global__ __launch_bounds__(256) void gemm_bias_kernel(
    const float* __restrict__ A, const float* __restrict__ W,
    const float* __restrict__ bias, float* __restrict__ C,
    int Kdim, int Ndim)
{
    __shared__ float As[16 * 68];
    __shared__ float Bs[16 * 68];

    const int tid = threadIdx.x;
    const int tx  = tid & 15;
    const int ty  = tid >> 4;
    const int m0  = blockIdx.x * 64;
    const int n0  = blockIdx.y * 64;

    const int lrow = tid >> 2;          // 0..63
    const int lc4  = (tid & 3) << 2;    // 0,4,8,12

    const float* Ap = A + (size_t)(m0 + lrow) * Kdim + lc4;
    const float* Wp = W + (size_t)(n0 + lrow) * Kdim + lc4;

    float acc[4][4] = {};

    for (int k0 = 0; k0 < Kdim; k0 += 16) {
        const float4 av = *(const float4*)(Ap + k0);
        const float4 wv = *(const float4*)(Wp + k0);
        __syncthreads();   // previous compute phase done before overwrite
        As[(lc4 + 0) * 68 + lrow] = av.x;
        As[(lc4 + 1) * 68 + lrow] = av.y;
        As[(lc4 + 2) * 68 + lrow] = av.z;
        As[(lc4 + 3) * 68 + lrow] = av.w;
        Bs[(lc4 + 0) * 68 + lrow] = wv.x;
        Bs[(lc4 + 1) * 68 + lrow] = wv.y;
        Bs[(lc4 + 2) * 68 + lrow] = wv.z;
        Bs[(lc4 + 3) * 68 + lrow] = wv.w;
        __syncthreads();

#pragma unroll
        for (int kk = 0; kk < 16; kk++) {
            const float4 a4 = *(const float4*)&As[kk * 68 + ty * 4];
            const float4 b4 = *(const float4*)&Bs[kk * 68 + tx * 4];
            const float* ap = (const float*)&a4;
            const float* bp = (const float*)&b4;
#pragma unroll
            for (int i = 0; i < 4; i++)
#pragma unroll
                for (int j = 0; j < 4; j++)
                    acc[i][j] += ap[i] * bp[j];
        }
    }

    const int n = n0 + tx * 4;
    const float4 bv = *(const float4*)(bias + n);
    const float* bp = (const float*)&bv;

#pragma unroll
    for (int i = 0; i < 4; i++) {
        const int m = m0 + ty * 4 + i;
        float4 o;
        float* op = (float*)&o;
#pragma unroll
        for (int j = 0; j < 4; j++) op[j] = acc[i][j] + bp[j];

        if (MODE == 0) {
            *(float4*)(C + (size_t)m * Ndim + n) = o;
        } else {
            const int bidx = m >> 11;          // m / S_
            const int srow = m & (S_ - 1);
            const int h    = n >> 6;           // n / DK_
            const int dk   = n & 63;
            *(float4*)(C + (((size_t)(bidx * H_ + h)) * S_ + srow) * DK_ + dk) = o;
        }
    }
}

// ---------------------------------------------------------------------------
// Fused attention, one (b,h) head slice and 64-query tile per CTA.
// Online softmax; P tile staged through smem aliasing the K tile.
// Mask semantics: mask[b,q]==0 masks the whole query row -> reference softmax
// over all -1e9 is exactly uniform; we reproduce this exactly by zeroing the
// row's scores (softmax of all-zeros is also exactly uniform).
// Output written directly in concat [b, s, d] layout.
// ---------------------------------------------------------------------------
__device__ __forceinline__ float red16_max(float v) {
#pragma unroll
    for (int o = 8; o >= 1; o >>= 1)
        v = fmaxf(v, __shfl_xor_sync(0xffffffffu, v, o));
    return v;
}
__device__ __forceinline__ float red16_sum(float v) {
#pragma unroll
    for (int o = 8; o >= 1; o >>= 1)
        v += __shfl_xor_sync(0xffffffffu, v, o);
    return v;
}

__global__ __launch_bounds__(256) void attn_kernel(
    const int* __restrict__ mask, float* __restrict__ Cc)
{
    extern __shared__ float sm[];
    float* Qs = sm;                  // [64 d][68]  (d-major)
    float* KP = sm + 64 * 68;        // [64][68]    K d-major / P key-major
    float* Vs = sm + 2 * 64 * 68;    // [64 key][64 dim]

    const int tid = threadIdx.x;
    const int tx  = tid & 15;
    const int ty  = tid >> 4;
    const int q0  = blockIdx.x * 64;
    const int bh  = blockIdx.y;
    const int b   = bh / H_;
    const int h   = bh - b * H_;

    const float* Qg = g_Q + (size_t)bh * S_ * DK_;
    const float* Kg = g_K + (size_t)bh * S_ * DK_;
    const float* Vg = g_V + (size_t)bh * S_ * DK_;

    const int lq = tid >> 2;          // 0..63 (row within tile)
    const int lc = (tid & 3) << 4;    // 0,16,32,48 (dim chunk base)

    // Load Q tile transposed into smem (d-major)
#pragma unroll
    for (int i = 0; i < 4; i++) {
        const float4 v = *(const float4*)(Qg + (size_t)(q0 + lq) * DK_ + lc + 4 * i);
        Qs[(lc + 4 * i + 0) * 68 + lq] = v.x;
        Qs[(lc + 4 * i + 1) * 68 + lq] = v.y;
        Qs[(lc + 4 * i + 2) * 68 + lq] = v.z;
        Qs[(lc + 4 * i + 3) * 68 + lq] = v.w;
    }

    float qscale[4];
#pragma unroll
    for (int i = 0; i < 4; i++)
        qscale[i] = mask[b * S_ + q0 + ty * 4 + i] ? 0.125f : 0.0f;  // 1/sqrt(64)

    float mrun[4], lrun[4], acc[4][4] = {};
#pragma unroll
    for (int i = 0; i < 4; i++) { mrun[i] = -1e30f; lrun[i] = 0.0f; }

    for (int k0 = 0; k0 < S_; k0 += 64) {
        // Load K (transposed, d-major) and V (natural) tiles
#pragma unroll
        for (int i = 0; i < 4; i++) {
            const float4 kv = *(const float4*)(Kg + (size_t)(k0 + lq) * DK_ + lc + 4 * i);
            KP[(lc + 4 * i + 0) * 68 + lq] = kv.x;
            KP[(lc + 4 * i + 1) * 68 + lq] = kv.y;
            KP[(lc + 4 * i + 2) * 68 + lq] = kv.z;
            KP[(lc + 4 * i + 3) * 68 + lq] = kv.w;
            const float4 vv = *(const float4*)(Vg + (size_t)(k0 + lq) * DK_ + lc + 4 * i);
            *(float4*)&Vs[lq * 64 + lc + 4 * i] = vv;
        }
        __syncthreads();

        // Scores: S = Q @ K^T
        float s[4][4] = {};
#pragma unroll 16
        for (int d = 0; d < 64; d++) {
            const float4 a4 = *(const float4*)&Qs[d * 68 + ty * 4];
            const float4 b4 = *(const float4*)&KP[d * 68 + tx * 4];
            const float* ap = (const float*)&a4;
            const float* bp = (const float*)&b4;
#pragma unroll
            for (int i = 0; i < 4; i++)
#pragma unroll
                for (int j = 0; j < 4; j++)
                    s[i][j] += ap[i] * bp[j];
        }

        // Online softmax per query row (16 lanes own a row group)
#pragma unroll
        for (int i = 0; i < 4; i++) {
            const float sc = qscale[i];
#pragma unroll
            for (int j = 0; j < 4; j++) s[i][j] *= sc;
            float mx = fmaxf(fmaxf(s[i][0], s[i][1]), fmaxf(s[i][2], s[i][3]));
            mx = red16_max(mx);
            const float mnew = fmaxf(mrun[i], mx);
            const float corr = __expf(mrun[i] - mnew);
            mrun[i] = mnew;
            float ls = 0.0f;
#pragma unroll
            for (int j = 0; j < 4; j++) {
                const float p = __expf(s[i][j] - mnew);
                s[i][j] = p;
                ls += p;
            }
            ls = red16_sum(ls);
            lrun[i] = lrun[i] * corr + ls;
#pragma unroll
            for (int j = 0; j < 4; j++) acc[i][j] *= corr;
        }
        __syncthreads();   // everyone done reading K before P overwrite

        // Write P transposed (key-major) into the K tile's smem
#pragma unroll
        for (int j = 0; j < 4; j++) {
            const float4 pv = make_float4(s[0][j], s[1][j], s[2][j], s[3][j]);
            *(float4*)&KP[(tx * 4 + j) * 68 + ty * 4] = pv;
        }
        __syncthreads();

        // O += P @ V
#pragma unroll 16
        for (int k = 0; k < 64; k++) {
            const float4 a4 = *(const float4*)&KP[k * 68 + ty * 4];
            const float4 b4 = *(const float4*)&Vs[k * 64 + tx * 4];
            const float* ap = (const float*)&a4;
            const float* bp = (const float*)&b4;
#pragma unroll
            for (int i = 0; i < 4; i++)
#pragma unroll
                for (int j = 0; j < 4; j++)
                    acc[i][j] += ap[i] * bp[j];
        }
        __syncthreads();   // done with KP/Vs before next tile's loads
    }

    // Epilogue: normalize and write to concat [b, s, d] layout
#pragma unroll
    for (int i = 0; i < 4; i++) {
        const float inv = 1.0f / lrun[i];
        float4 o;
        float* op = (float*)&o;
#pragma unroll
        for (int j = 0; j < 4; j++) op[j] = acc[i][j] * inv;
        const size_t row = (size_t)b * S_ + q0 + ty * 4 + i;
        *(float4*)(Cc + row * D_ + h * DK_ + tx * 4) = o;
    }
}

// ---------------------------------------------------------------------------
extern "C" void kernel_launch(void* const* d_in, const int* in_sizes, int n_in,
                              void* d_out, int out_size)
{
    const float* q    = (const float*)d_in[0];
    const float* k    = (const float*)d_in[1];
    const float* v    = (const float*)d_in[2];
    const int*   mask = (const int*)  d_in[3];
    const float* Wq   = (const float*)d_in[4];
    const float* bq   = (const float*)d_in[5];
    const float* Wk   = (const float*)d_in[6];
    const float* bk   = (const float*)d_in[7];
    const float* Wv   = (const float*)d_in[8];
    const float* bv   = (const float*)d_in[9];
    const float* Wo   = (const float*)d_in[10];
    const float* bo   = (const float*)d_in[11];
    float* out = (float*)d_out;

    void *pQ, *pK, *pV, *pC;
    cudaGetSymbolAddress(&pQ, g_Q);
    cudaGetSymbolAddress(&pK, g_K);
    cudaGetSymbolAddress(&pV, g_V);
    cudaGetSymbolAddress(&pC, g_C);

    const dim3 blk(256);
    const dim3 gGemm(M_ / 64, D_ / 64);

    // Q/K/V projections, written directly in [b,h,s,dk] layout
    gemm_bias_kernel<1><<<gGemm, blk>>>(q, Wq, bq, (float*)pQ, D_, D_);
    gemm_bias_kernel<1><<<gGemm, blk>>>(k, Wk, bk, (float*)pK, D_, D_);
    gemm_bias_kernel<1><<<gGemm, blk>>>(v, Wv, bv, (float*)pV, D_, D_);

    // Fused attention -> concat layout
    const int smem = (2 * 64 * 68 + 64 * 64) * (int)sizeof(float);  // 51200 B
    cudaFuncSetAttribute(attn_kernel, cudaFuncAttributeMaxDynamicSharedMemorySize, smem);
    attn_kernel<<<dim3(S_ / 64, B_ * H_), blk, smem>>>(mask, (float*)pC);

    // Output projection
    gemm_bias_kernel<0><<<gGemm, blk>>>((const float*)pC, Wo, bo, out, D_, D_);
}

// round 2
// speedup vs baseline: 3.0195x; 3.0195x over previous
#include <cuda_runtime.h>
#include <cstdint>

// Problem constants
#define B_  4
#define S_  2048
#define D_  768
#define H_  12
#define DK_ 64
#define M_  (B_ * S_)   // 8192

// Scratch (module-static device memory; no runtime allocation)
__device__ float g_Q[(size_t)B_ * H_ * S_ * DK_];
__device__ float g_K[(size_t)B_ * H_ * S_ * DK_];
__device__ float g_V[(size_t)B_ * H_ * S_ * DK_];
__device__ float g_C[(size_t)M_ * D_];

// ---------------------------------------------------------------------------
// TF32 helpers
// ---------------------------------------------------------------------------
__device__ __forceinline__ uint32_t f2tf(float f) {
    uint32_t r;
    asm("cvt.rna.tf32.f32 %0, %1;" : "=r"(r) : "f"(f));
    return r;
}

// D += A(16x8 row) * B(8x8 col), tf32 inputs, fp32 accumulate
__device__ __forceinline__ void mma8(float* c, const uint32_t* a, const uint32_t* b) {
    asm volatile(
        "mma.sync.aligned.m16n8k8.row.col.f32.tf32.tf32.f32 "
        "{%0,%1,%2,%3},{%4,%5,%6,%7},{%8,%9},{%0,%1,%2,%3};"
        : "+f"(c[0]), "+f"(c[1]), "+f"(c[2]), "+f"(c[3])
        : "r"(a[0]), "r"(a[1]), "r"(a[2]), "r"(a[3]), "r"(b[0]), "r"(b[1]));
}

// ---------------------------------------------------------------------------
// GEMM: C = A[M,K] @ W[N,K]^T + bias[N]   (tf32 tensor cores)
// BM=128, BN=128, BK=32. 256 threads = 8 warps, warp tile 32x64.
// smem stride 36 floats -> conflict-free fragment loads ((4r + t4) mod 32).
// MODE 0: C row-major [M, N];  MODE 1: C written as [b, h, s, dk].
// ---------------------------------------------------------------------------
template <int MODE>
__global__ __launch_bounds__(256) void gemm_tc_kernel(
    const float* __restrict__ A, const float* __restrict__ W,
    const float* __restrict__ bias, float* __restrict__ C,
    int Kdim, int Ndim)
{
    __shared__ uint32_t As[128 * 36];
    __shared__ uint32_t Bs[128 * 36];

    const int tid  = threadIdx.x;
    const int lane = tid & 31;
    const int wid  = tid >> 5;
    const int g    = lane >> 2;
    const int t4   = lane & 3;
    const int wm   = wid >> 1;        // 0..3 -> 32-row slice
    const int wn   = wid & 1;         // 0..1 -> 64-col slice
    const int m0   = blockIdx.x * 128;
    const int n0   = blockIdx.y * 128;

    const int ro = tid >> 3;          // 0..31
    const int ch = (tid & 7) * 4;     // 0..28

    float acc[2][8][4] = {};

    for (int k0 = 0; k0 < Kdim; k0 += 32) {
        __syncthreads();
#pragma unroll
        for (int i = 0; i < 4; i++) {
            const int r = ro + i * 32;
            const float4 av = *(const float4*)(A + (size_t)(m0 + r) * Kdim + k0 + ch);
            uint4 ua = make_uint4(f2tf(av.x), f2tf(av.y), f2tf(av.z), f2tf(av.w));
            *(uint4*)&As[r * 36 + ch] = ua;
            const float4 wv = *(const float4*)(W + (size_t)(n0 + r) * Kdim + k0 + ch);
            uint4 uw = make_uint4(f2tf(wv.x), f2tf(wv.y), f2tf(wv.z), f2tf(wv.w));
            *(uint4*)&Bs[r * 36 + ch] = uw;
        }
        __syncthreads();

#pragma unroll
        for (int kf = 0; kf < 4; kf++) {
            uint32_t a[2][4];
#pragma unroll
            for (int mf = 0; mf < 2; mf++) {
                const int r = wm * 32 + mf * 16 + g;
                a[mf][0] = As[r * 36 + kf * 8 + t4];
                a[mf][1] = As[(r + 8) * 36 + kf * 8 + t4];
                a[mf][2] = As[r * 36 + kf * 8 + t4 + 4];
                a[mf][3] = As[(r + 8) * 36 + kf * 8 + t4 + 4];
            }
            uint32_t b[8][2];
#pragma unroll
            for (int nf = 0; nf < 8; nf++) {
                const int r = wn * 64 + nf * 8 + g;
                b[nf][0] = Bs[r * 36 + kf * 8 + t4];
                b[nf][1] = Bs[r * 36 + kf * 8 + t4 + 4];
            }
#pragma unroll
            for (int mf = 0; mf < 2; mf++)
#pragma unroll
                for (int nf = 0; nf < 8; nf++)
                    mma8(acc[mf][nf], a[mf], b[nf]);
        }
    }

    // Epilogue
#pragma unroll
    for (int mf = 0; mf < 2; mf++) {
#pragma unroll
        for (int nf = 0; nf < 8; nf++) {
            const int n = n0 + wn * 64 + nf * 8 + 2 * t4;
            const float b0 = bias[n];
            const float b1 = bias[n + 1];
#pragma unroll
            for (int rr = 0; rr < 2; rr++) {
                const int m = m0 + wm * 32 + mf * 16 + g + rr * 8;
                float2 o;
                o.x = acc[mf][nf][2 * rr + 0] + b0;
                o.y = acc[mf][nf][2 * rr + 1] + b1;
                if (MODE == 0) {
                    *(float2*)(C + (size_t)m * Ndim + n) = o;
                } else {
                    const int bidx = m >> 11;
                    const int srow = m & (S_ - 1);
                    const int h    = n >> 6;
                    const int dk   = n & 63;
                    *(float2*)(C + (((size_t)(bidx * H_ + h)) * S_ + srow) * DK_ + dk) = o;
                }
            }
        }
    }
}

// ---------------------------------------------------------------------------
// Fused flash attention (tf32 tensor cores).
// CTA: 128 queries x one (b,h). 8 warps, each owns 16 full query rows.
// Q fragments pre-scaled (mask? 1/8 : 0) and held in registers for the whole
// K loop. K row-major, V transposed, P via smem; stride 68 -> conflict-free.
// Masked rows: S row == 0 -> softmax exactly uniform == reference (-1e9 rows).
// ---------------------------------------------------------------------------
#define TQ 128
#define TK 64
#define AT_STR 68

__global__ __launch_bounds__(256) void attn_kernel(
    const int* __restrict__ mask, float* __restrict__ Cc)
{
    extern __shared__ uint32_t sm[];
    uint32_t* Ks = sm;                     // [64 key][68]   (tf32)
    uint32_t* Vt = sm + 64 * AT_STR;       // [64 d][68]     (tf32, transposed)
    uint32_t* Ps = sm + 2 * 64 * AT_STR;   // [128 q][68]    (tf32)

    const int tid  = threadIdx.x;
    const int lane = tid & 31;
    const int wid  = tid >> 5;
    const int g    = lane >> 2;
    const int t4   = lane & 3;
    const int q0   = blockIdx.x * TQ;
    const int bh   = blockIdx.y;
    const int b    = bh / H_;
    const int h    = bh - b * H_;

    const float* Qg = g_Q + (size_t)bh * S_ * DK_;
    const float* Kg = g_K + (size_t)bh * S_ * DK_;
    const float* Vg = g_V + (size_t)bh * S_ * DK_;

    const int row0 = wid * 16 + g;     // warp-local rows
    const int row1 = row0 + 8;

    const float sc0 = mask[b * S_ + q0 + row0] ? 0.125f : 0.0f;  // 1/sqrt(64)
    const float sc1 = mask[b * S_ + q0 + row1] ? 0.125f : 0.0f;

    // Q fragments in registers for the whole loop (scale folded in)
    uint32_t qa[8][4];
#pragma unroll
    for (int kf = 0; kf < 8; kf++) {
        qa[kf][0] = f2tf(Qg[(size_t)(q0 + row0) * DK_ + kf * 8 + t4] * sc0);
        qa[kf][1] = f2tf(Qg[(size_t)(q0 + row1) * DK_ + kf * 8 + t4] * sc1);
        qa[kf][2] = f2tf(Qg[(size_t)(q0 + row0) * DK_ + kf * 8 + t4 + 4] * sc0);
        qa[kf][3] = f2tf(Qg[(size_t)(q0 + row1) * DK_ + kf * 8 + t4 + 4] * sc1);
    }

    float mr0 = -1e30f, mr1 = -1e30f, l0 = 0.0f, l1 = 0.0f;
    float oacc[8][4] = {};

    const int key = tid >> 2;        // 0..63
    const int dc  = (tid & 3) * 16;  // 0,16,32,48

    for (int k0 = 0; k0 < S_; k0 += TK) {
        __syncthreads();   // previous iteration's reads of Ks/Vt done
        // Load K (row-major) and V (transposed) tiles, convert to tf32
#pragma unroll
        for (int i = 0; i < 4; i++) {
            const float4 kv = *(const float4*)(Kg + (size_t)(k0 + key) * DK_ + dc + 4 * i);
            uint4 uk = make_uint4(f2tf(kv.x), f2tf(kv.y), f2tf(kv.z), f2tf(kv.w));
            *(uint4*)&Ks[key * AT_STR + dc + 4 * i] = uk;
            const float4 vv = *(const float4*)(Vg + (size_t)(k0 + key) * DK_ + dc + 4 * i);
            Vt[(dc + 4 * i + 0) * AT_STR + key] = f2tf(vv.x);
            Vt[(dc + 4 * i + 1) * AT_STR + key] = f2tf(vv.y);
            Vt[(dc + 4 * i + 2) * AT_STR + key] = f2tf(vv.z);
            Vt[(dc + 4 * i + 3) * AT_STR + key] = f2tf(vv.w);
        }
        __syncthreads();

        // S = Q @ K^T  (warp: 16 rows x 64 keys)
        float sacc[8][4] = {};
#pragma unroll
        for (int kf = 0; kf < 8; kf++) {
            uint32_t kb[8][2];
#pragma unroll
            for (int nf = 0; nf < 8; nf++) {
                const int r = nf * 8 + g;
                kb[nf][0] = Ks[r * AT_STR + kf * 8 + t4];
                kb[nf][1] = Ks[r * AT_STR + kf * 8 + t4 + 4];
            }
#pragma unroll
            for (int nf = 0; nf < 8; nf++)
                mma8(sacc[nf], qa[kf], kb[nf]);
        }

        // Online softmax (rows row0/row1; reduce across quad lanes t4)
        float mx0 = -1e30f, mx1 = -1e30f;
#pragma unroll
        for (int nf = 0; nf < 8; nf++) {
            mx0 = fmaxf(mx0, fmaxf(sacc[nf][0], sacc[nf][1]));
            mx1 = fmaxf(mx1, fmaxf(sacc[nf][2], sacc[nf][3]));
        }
        mx0 = fmaxf(mx0, __shfl_xor_sync(0xffffffffu, mx0, 1));
        mx0 = fmaxf(mx0, __shfl_xor_sync(0xffffffffu, mx0, 2));
        mx1 = fmaxf(mx1, __shfl_xor_sync(0xffffffffu, mx1, 1));
        mx1 = fmaxf(mx1, __shfl_xor_sync(0xffffffffu, mx1, 2));

        const float mn0 = fmaxf(mr0, mx0);
        const float mn1 = fmaxf(mr1, mx1);
        const float c0 = __expf(mr0 - mn0);
        const float c1 = __expf(mr1 - mn1);
        mr0 = mn0; mr1 = mn1;

        float s0 = 0.0f, s1 = 0.0f;
#pragma unroll
        for (int nf = 0; nf < 8; nf++) {
            sacc[nf][0] = __expf(sacc[nf][0] - mn0);
            sacc[nf][1] = __expf(sacc[nf][1] - mn0);
            sacc[nf][2] = __expf(sacc[nf][2] - mn1);
            sacc[nf][3] = __expf(sacc[nf][3] - mn1);
            s0 += sacc[nf][0] + sacc[nf][1];
            s1 += sacc[nf][2] + sacc[nf][3];
        }
        s0 += __shfl_xor_sync(0xffffffffu, s0, 1);
        s0 += __shfl_xor_sync(0xffffffffu, s0, 2);
        s1 += __shfl_xor_sync(0xffffffffu, s1, 1);
        s1 += __shfl_xor_sync(0xffffffffu, s1, 2);
        l0 = l0 * c0 + s0;
        l1 = l1 * c1 + s1;

#pragma unroll
        for (int nf = 0; nf < 8; nf++) {
            oacc[nf][0] *= c0; oacc[nf][1] *= c0;
            oacc[nf][2] *= c1; oacc[nf][3] *= c1;
        }

        // P rows are warp-private -> warp-level sync only
        __syncwarp();
#pragma unroll
        for (int nf = 0; nf < 8; nf++) {
            uint2 u0 = make_uint2(f2tf(sacc[nf][0]), f2tf(sacc[nf][1]));
            *(uint2*)&Ps[row0 * AT_STR + nf * 8 + 2 * t4] = u0;
            uint2 u1 = make_uint2(f2tf(sacc[nf][2]), f2tf(sacc[nf][3]));
            *(uint2*)&Ps[row1 * AT_STR + nf * 8 + 2 * t4] = u1;
        }
        __syncwarp();

        // O += P @ V  (warp: 16 rows x 64 dims)
#pragma unroll
        for (int kf = 0; kf < 8; kf++) {
            uint32_t pa[4];
            pa[0] = Ps[row0 * AT_STR + kf * 8 + t4];
            pa[1] = Ps[row1 * AT_STR + kf * 8 + t4];
            pa[2] = Ps[row0 * AT_STR + kf * 8 + t4 + 4];
            pa[3] = Ps[row1 * AT_STR + kf * 8 + t4 + 4];
#pragma unroll
            for (int nf = 0; nf < 8; nf++) {
                uint32_t vb[2];
                vb[0] = Vt[(nf * 8 + g) * AT_STR + kf * 8 + t4];
                vb[1] = Vt[(nf * 8 + g) * AT_STR + kf * 8 + t4 + 4];
                mma8(oacc[nf], pa, vb);
            }
        }
    }

    // Epilogue: normalize, write concat [b, s, d] layout
    const float inv0 = 1.0f / l0;
    const float inv1 = 1.0f / l1;
    const size_t base0 = ((size_t)b * S_ + q0 + row0) * D_ + h * DK_;
    const size_t base1 = ((size_t)b * S_ + q0 + row1) * D_ + h * DK_;
#pragma unroll
    for (int nf = 0; nf < 8; nf++) {
        float2 o0 = make_float2(oacc[nf][0] * inv0, oacc[nf][1] * inv0);
        *(float2*)(Cc + base0 + nf * 8 + 2 * t4) = o0;
        float2 o1 = make_float2(oacc[nf][2] * inv1, oacc[nf][3] * inv1);
        *(float2*)(Cc + base1 + nf * 8 + 2 * t4) = o1;
    }
}

// ---------------------------------------------------------------------------
extern "C" void kernel_launch(void* const* d_in, const int* in_sizes, int n_in,
                              void* d_out, int out_size)
{
    const float* q    = (const float*)d_in[0];
    const float* k    = (const float*)d_in[1];
    const float* v    = (const float*)d_in[2];
    const int*   mask = (const int*)  d_in[3];
    const float* Wq   = (const float*)d_in[4];
    const float* bq   = (const float*)d_in[5];
    const float* Wk   = (const float*)d_in[6];
    const float* bk   = (const float*)d_in[7];
    const float* Wv   = (const float*)d_in[8];
    const float* bv   = (const float*)d_in[9];
    const float* Wo   = (const float*)d_in[10];
    const float* bo   = (const float*)d_in[11];
    float* out = (float*)d_out;

    void *pQ, *pK, *pV, *pC;
    cudaGetSymbolAddress(&pQ, g_Q);
    cudaGetSymbolAddress(&pK, g_K);
    cudaGetSymbolAddress(&pV, g_V);
    cudaGetSymbolAddress(&pC, g_C);

    const dim3 blk(256);
    const dim3 gGemm(M_ / 128, D_ / 128);

    // Q/K/V projections, written directly in [b,h,s,dk] layout
    gemm_tc_kernel<1><<<gGemm, blk>>>(q, Wq, bq, (float*)pQ, D_, D_);
    gemm_tc_kernel<1><<<gGemm, blk>>>(k, Wk, bk, (float*)pK, D_, D_);
    gemm_tc_kernel<1><<<gGemm, blk>>>(v, Wv, bv, (float*)pV, D_, D_);

    // Fused attention -> concat layout
    const int smem = (2 * 64 * AT_STR + TQ * AT_STR) * (int)sizeof(uint32_t);  // 69632 B
    cudaFuncSetAttribute(attn_kernel, cudaFuncAttributeMaxDynamicSharedMemorySize, smem);
    attn_kernel<<<dim3(S_ / TQ, B_ * H_), blk, smem>>>(mask, (float*)pC);

    // Output projection
    gemm_tc_kernel<0><<<gGemm, blk>>>((const float*)pC, Wo, bo, out, D_, D_);
}

// round 3
// speedup vs baseline: 3.0634x; 1.0145x over previous
#include <cuda_runtime.h>
#include <cstdint>

// Problem constants
#define B_  4
#define S_  2048
#define D_  768
#define H_  12
#define DK_ 64
#define M_  (B_ * S_)   // 8192

// Scratch (module-static device memory; no runtime allocation)
__device__ float g_Q[(size_t)B_ * H_ * S_ * DK_];
__device__ float g_K[(size_t)B_ * H_ * S_ * DK_];
__device__ float g_V[(size_t)B_ * H_ * S_ * DK_];
__device__ float g_C[(size_t)M_ * D_];

// ---------------------------------------------------------------------------
// TF32 helpers
// ---------------------------------------------------------------------------
__device__ __forceinline__ uint32_t f2tf(float f) {
    uint32_t r;
    asm("cvt.rna.tf32.f32 %0, %1;" : "=r"(r) : "f"(f));
    return r;
}

// D += A(16x8 row) * B(8x8 col), tf32 inputs, fp32 accumulate
__device__ __forceinline__ void mma8(float* c, const uint32_t* a, const uint32_t* b) {
    asm volatile(
        "mma.sync.aligned.m16n8k8.row.col.f32.tf32.tf32.f32 "
        "{%0,%1,%2,%3},{%4,%5,%6,%7},{%8,%9},{%0,%1,%2,%3};"
        : "+f"(c[0]), "+f"(c[1]), "+f"(c[2]), "+f"(c[3])
        : "r"(a[0]), "r"(a[1]), "r"(a[2]), "r"(a[3]), "r"(b[0]), "r"(b[1]));
}

// ---------------------------------------------------------------------------
// GEMM: C = A[M,K] @ W[N,K]^T + bias[N]   (tf32 tensor cores)
// BM=128, BN=128, BK=32. 256 threads = 8 warps, warp tile 32x64.
// smem stride 36 floats -> conflict-free fragment loads ((4r + t4) mod 32).
// MODE 0: C row-major [M, N];  MODE 1: C written as [b, h, s, dk].
// ---------------------------------------------------------------------------
template <int MODE>
__global__ __launch_bounds__(256) void gemm_tc_kernel(
    const float* __restrict__ A, const float* __restrict__ W,
    const float* __restrict__ bias, float* __restrict__ C,
    int Kdim, int Ndim)
{
    __shared__ uint32_t As[128 * 36];
    __shared__ uint32_t Bs[128 * 36];

    const int tid  = threadIdx.x;
    const int lane = tid & 31;
    const int wid  = tid >> 5;
    const int g    = lane >> 2;
    const int t4   = lane & 3;
    const int wm   = wid >> 1;        // 0..3 -> 32-row slice
    const int wn   = wid & 1;         // 0..1 -> 64-col slice
    const int m0   = blockIdx.x * 128;
    const int n0   = blockIdx.y * 128;

    const int ro = tid >> 3;          // 0..31
    const int ch = (tid & 7) * 4;     // 0..28

    float acc[2][8][4] = {};

    for (int k0 = 0; k0 < Kdim; k0 += 32) {
        __syncthreads();
#pragma unroll
        for (int i = 0; i < 4; i++) {
            const int r = ro + i * 32;
            const float4 av = *(const float4*)(A + (size_t)(m0 + r) * Kdim + k0 + ch);
            uint4 ua = make_uint4(f2tf(av.x), f2tf(av.y), f2tf(av.z), f2tf(av.w));
            *(uint4*)&As[r * 36 + ch] = ua;
            const float4 wv = *(const float4*)(W + (size_t)(n0 + r) * Kdim + k0 + ch);
            uint4 uw = make_uint4(f2tf(wv.x), f2tf(wv.y), f2tf(wv.z), f2tf(wv.w));
            *(uint4*)&Bs[r * 36 + ch] = uw;
        }
        __syncthreads();

#pragma unroll
        for (int kf = 0; kf < 4; kf++) {
            uint32_t a[2][4];
#pragma unroll
            for (int mf = 0; mf < 2; mf++) {
                const int r = wm * 32 + mf * 16 + g;
                a[mf][0] = As[r * 36 + kf * 8 + t4];
                a[mf][1] = As[(r + 8) * 36 + kf * 8 + t4];
                a[mf][2] = As[r * 36 + kf * 8 + t4 + 4];
                a[mf][3] = As[(r + 8) * 36 + kf * 8 + t4 + 4];
            }
            uint32_t b[8][2];
#pragma unroll
            for (int nf = 0; nf < 8; nf++) {
                const int r = wn * 64 + nf * 8 + g;
                b[nf][0] = Bs[r * 36 + kf * 8 + t4];
                b[nf][1] = Bs[r * 36 + kf * 8 + t4 + 4];
            }
#pragma unroll
            for (int mf = 0; mf < 2; mf++)
#pragma unroll
                for (int nf = 0; nf < 8; nf++)
                    mma8(acc[mf][nf], a[mf], b[nf]);
        }
    }

    // Epilogue
#pragma unroll
    for (int mf = 0; mf < 2; mf++) {
#pragma unroll
        for (int nf = 0; nf < 8; nf++) {
            const int n = n0 + wn * 64 + nf * 8 + 2 * t4;
            const float b0 = bias[n];
            const float b1 = bias[n + 1];
#pragma unroll
            for (int rr = 0; rr < 2; rr++) {
                const int m = m0 + wm * 32 + mf * 16 + g + rr * 8;
                float2 o;
                o.x = acc[mf][nf][2 * rr + 0] + b0;
                o.y = acc[mf][nf][2 * rr + 1] + b1;
                if (MODE == 0) {
                    *(float2*)(C + (size_t)m * Ndim + n) = o;
                } else {
                    const int bidx = m >> 11;
                    const int srow = m & (S_ - 1);
                    const int h    = n >> 6;
                    const int dk   = n & 63;
                    *(float2*)(C + (((size_t)(bidx * H_ + h)) * S_ + srow) * DK_ + dk) = o;
                }
            }
        }
    }
}

// ---------------------------------------------------------------------------
// Fused flash attention (tf32 tensor cores).
// CTA: 128 queries x one (b,h). 8 warps, each owns 16 full query rows.
// Q fragments pre-scaled (mask? 1/8 : 0) and held in registers for the whole
// K loop. K row-major, V transposed, P via smem; stride 68 -> conflict-free.
// Masked rows: S row == 0 -> softmax exactly uniform == reference (-1e9 rows).
// ---------------------------------------------------------------------------
#define TQ 128
#define TK 64
#define AT_STR 68

__global__ __launch_bounds__(256) void attn_kernel(
    const int* __restrict__ mask, float* __restrict__ Cc)
{
    extern __shared__ uint32_t sm[];
    uint32_t* Ks = sm;                     // [64 key][68]   (tf32)
    uint32_t* Vt = sm + 64 * AT_STR;       // [64 d][68]     (tf32, transposed)
    uint32_t* Ps = sm + 2 * 64 * AT_STR;   // [128 q][68]    (tf32)

    const int tid  = threadIdx.x;
    const int lane = tid & 31;
    const int wid  = tid >> 5;
    const int g    = lane >> 2;
    const int t4   = lane & 3;
    const int q0   = blockIdx.x * TQ;
    const int bh   = blockIdx.y;
    const int b    = bh / H_;
    const int h    = bh - b * H_;

    const float* Qg = g_Q + (size_t)bh * S_ * DK_;
    const float* Kg = g_K + (size_t)bh * S_ * DK_;
    const float* Vg = g_V + (size_t)bh * S_ * DK_;

    const int row0 = wid * 16 + g;     // warp-local rows
    const int row1 = row0 + 8;

    const float sc0 = mask[b * S_ + q0 + row0] ? 0.125f : 0.0f;  // 1/sqrt(64)
    const float sc1 = mask[b * S_ + q0 + row1] ? 0.125f : 0.0f;

    // Q fragments in registers for the whole loop (scale folded in)
    uint32_t qa[8][4];
#pragma unroll
    for (int kf = 0; kf < 8; kf++) {
        qa[kf][0] = f2tf(Qg[(size_t)(q0 + row0) * DK_ + kf * 8 + t4] * sc0);
        qa[kf][1] = f2tf(Qg[(size_t)(q0 + row1) * DK_ + kf * 8 + t4] * sc1);
        qa[kf][2] = f2tf(Qg[(size_t)(q0 + row0) * DK_ + kf * 8 + t4 + 4] * sc0);
        qa[kf][3] = f2tf(Qg[(size_t)(q0 + row1) * DK_ + kf * 8 + t4 + 4] * sc1);
    }

    float mr0 = -1e30f, mr1 = -1e30f, l0 = 0.0f, l1 = 0.0f;
    float oacc[8][4] = {};

    const int key = tid >> 2;        // 0..63
    const int dc  = (tid & 3) * 16;  // 0,16,32,48

    for (int k0 = 0; k0 < S_; k0 += TK) {
        __syncthreads();   // previous iteration's reads of Ks/Vt done
        // Load K (row-major) and V (transposed) tiles, convert to tf32
#pragma unroll
        for (int i = 0; i < 4; i++) {
            const float4 kv = *(const float4*)(Kg + (size_t)(k0 + key) * DK_ + dc + 4 * i);
            uint4 uk = make_uint4(f2tf(kv.x), f2tf(kv.y), f2tf(kv.z), f2tf(kv.w));
            *(uint4*)&Ks[key * AT_STR + dc + 4 * i] = uk;
            const float4 vv = *(const float4*)(Vg + (size_t)(k0 + key) * DK_ + dc + 4 * i);
            Vt[(dc + 4 * i + 0) * AT_STR + key] = f2tf(vv.x);
            Vt[(dc + 4 * i + 1) * AT_STR + key] = f2tf(vv.y);
            Vt[(dc + 4 * i + 2) * AT_STR + key] = f2tf(vv.z);
            Vt[(dc + 4 * i + 3) * AT_STR + key] = f2tf(vv.w);
        }
        __syncthreads();

        // S = Q @ K^T  (warp: 16 rows x 64 keys)
        float sacc[8][4] = {};
#pragma unroll
        for (int kf = 0; kf < 8; kf++) {
            uint32_t kb[8][2];
#pragma unroll
            for (int nf = 0; nf < 8; nf++) {
                const int r = nf * 8 + g;
                kb[nf][0] = Ks[r * AT_STR + kf * 8 + t4];
                kb[nf][1] = Ks[r * AT_STR + kf * 8 + t4 + 4];
            }
#pragma unroll
            for (int nf = 0; nf < 8; nf++)
                mma8(sacc[nf], qa[kf], kb[nf]);
        }

        // Online softmax (rows row0/row1; reduce across quad lanes t4)
        float mx0 = -1e30f, mx1 = -1e30f;
#pragma unroll
        for (int nf = 0; nf < 8; nf++) {
            mx0 = fmaxf(mx0, fmaxf(sacc[nf][0], sacc[nf][1]));
            mx1 = fmaxf(mx1, fmaxf(sacc[nf][2], sacc[nf][3]));
        }
        mx0 = fmaxf(mx0, __shfl_xor_sync(0xffffffffu, mx0, 1));
        mx0 = fmaxf(mx0, __shfl_xor_sync(0xffffffffu, mx0, 2));
        mx1 = fmaxf(mx1, __shfl_xor_sync(0xffffffffu, mx1, 1));
        mx1 = fmaxf(mx1, __shfl_xor_sync(0xffffffffu, mx1, 2));

        const float mn0 = fmaxf(mr0, mx0);
        const float mn1 = fmaxf(mr1, mx1);
        const float c0 = __expf(mr0 - mn0);
        const float c1 = __expf(mr1 - mn1);
        mr0 = mn0; mr1 = mn1;

        float s0 = 0.0f, s1 = 0.0f;
#pragma unroll
        for (int nf = 0; nf < 8; nf++) {
            sacc[nf][0] = __expf(sacc[nf][0] - mn0);
            sacc[nf][1] = __expf(sacc[nf][1] - mn0);
            sacc[nf][2] = __expf(sacc[nf][2] - mn1);
            sacc[nf][3] = __expf(sacc[nf][3] - mn1);
            s0 += sacc[nf][0] + sacc[nf][1];
            s1 += sacc[nf][2] + sacc[nf][3];
        }
        s0 += __shfl_xor_sync(0xffffffffu, s0, 1);
        s0 += __shfl_xor_sync(0xffffffffu, s0, 2);
        s1 += __shfl_xor_sync(0xffffffffu, s1, 1);
        s1 += __shfl_xor_sync(0xffffffffu, s1, 2);
        l0 = l0 * c0 + s0;
        l1 = l1 * c1 + s1;

#pragma unroll
        for (int nf = 0; nf < 8; nf++) {
            oacc[nf][0] *= c0; oacc[nf][1] *= c0;
            oacc[nf][2] *= c1; oacc[nf][3] *= c1;
        }

        // P rows are warp-private -> warp-level sync only
        __syncwarp();
#pragma unroll
        for (int nf = 0; nf < 8; nf++) {
            uint2 u0 = make_uint2(f2tf(sacc[nf][0]), f2tf(sacc[nf][1]));
            *(uint2*)&Ps[row0 * AT_STR + nf * 8 + 2 * t4] = u0;
            uint2 u1 = make_uint2(f2tf(sacc[nf][2]), f2tf(sacc[nf][3]));
            *(uint2*)&Ps[row1 * AT_STR + nf * 8 + 2 * t4] = u1;
        }
        __syncwarp();

        // O += P @ V  (warp: 16 rows x 64 dims)
#pragma unroll
        for (int kf = 0; kf < 8; kf++) {
            uint32_t pa[4];
            pa[0] = Ps[row0 * AT_STR + kf * 8 + t4];
            pa[1] = Ps[row1 * AT_STR + kf * 8 + t4];
            pa[2] = Ps[row0 * AT_STR + kf * 8 + t4 + 4];
            pa[3] = Ps[row1 * AT_STR + kf * 8 + t4 + 4];
#pragma unroll
            for (int nf = 0; nf < 8; nf++) {
                uint32_t vb[2];
                vb[0] = Vt[(nf * 8 + g) * AT_STR + kf * 8 + t4];
                vb[1] = Vt[(nf * 8 + g) * AT_STR + kf * 8 + t4 + 4];
                mma8(oacc[nf], pa, vb);
            }
        }
    }

    // Epilogue: normalize, write concat [b, s, d] layout
    const float inv0 = 1.0f / l0;
    const float inv1 = 1.0f / l1;
    const size_t base0 = ((size_t)b * S_ + q0 + row0) * D_ + h * DK_;
    const size_t base1 = ((size_t)b * S_ + q0 + row1) * D_ + h * DK_;
#pragma unroll
    for (int nf = 0; nf < 8; nf++) {
        float2 o0 = make_float2(oacc[nf][0] * inv0, oacc[nf][1] * inv0);
        *(float2*)(Cc + base0 + nf * 8 + 2 * t4) = o0;
        float2 o1 = make_float2(oacc[nf][2] * inv1, oacc[nf][3] * inv1);
        *(float2*)(Cc + base1 + nf * 8 + 2 * t4) = o1;
    }
}

// ---------------------------------------------------------------------------
extern "C" void kernel_launch(void* const* d_in, const int* in_sizes, int n_in,
                              void* d_out, int out_size)
{
    const float* q    = (const float*)d_in[0];
    const float* k    = (const float*)d_in[1];
    const float* v    = (const float*)d_in[2];
    const int*   mask = (const int*)  d_in[3];
    const float* Wq   = (const float*)d_in[4];
    const float* bq   = (const float*)d_in[5];
    const float* Wk   = (const float*)d_in[6];
    const float* bk   = (const float*)d_in[7];
    const float* Wv   = (const float*)d_in[8];
    const float* bv   = (const float*)d_in[9];
    const float* Wo   = (const float*)d_in[10];
    const float* bo   = (const float*)d_in[11];
    float* out = (float*)d_out;

    void *pQ, *pK, *pV, *pC;
    cudaGetSymbolAddress(&pQ, g_Q);
    cudaGetSymbolAddress(&pK, g_K);
    cudaGetSymbolAddress(&pV, g_V);
    cudaGetSymbolAddress(&pC, g_C);

    const dim3 blk(256);
    const dim3 gGemm(M_ / 128, D_ / 128);

    // Q/K/V projections, written directly in [b,h,s,dk] layout
    gemm_tc_kernel<1><<<gGemm, blk>>>(q, Wq, bq, (float*)pQ, D_, D_);
    gemm_tc_kernel<1><<<gGemm, blk>>>(k, Wk, bk, (float*)pK, D_, D_);
    gemm_tc_kernel<1><<<gGemm, blk>>>(v, Wv, bv, (float*)pV, D_, D_);

    // Fused attention -> concat layout
    const int smem = (2 * 64 * AT_STR + TQ * AT_STR) * (int)sizeof(uint32_t);  // 69632 B
    cudaFuncSetAttribute(attn_kernel, cudaFuncAttributeMaxDynamicSharedMemorySize, smem);
    attn_kernel<<<dim3(S_ / TQ, B_ * H_), blk, smem>>>(mask, (float*)pC);

    // Output projection
    gemm_tc_kernel<0><<<gGemm, blk>>>((const float*)pC, Wo, bo, out, D_, D_);
}